// round 4
// baseline (speedup 1.0000x reference)
#include <cuda_runtime.h>
#include <cuda_fp16.h>
#include <math.h>
#include <stdint.h>

#define T 1024
#define H 1024
#define NH 8
#define NKV 4
#define HD 128
#define NE 32
#define MI 512
#define SI 1024

// ---------------- scratch ----------------
__device__ float g_qkv[T*2048];
__device__ float g_h2[T*H];
__device__ float g_xb[T*H];
__device__ float g_logits[T*NE];
__device__ float g_topkw[T*4];
__device__ int   g_cnt[NE];
__device__ int   g_list[NE*T];
__device__ float g_egu[4096*1024];
__device__ float g_edb[4096*1024];
__device__ float g_sgu[T*2048];
__device__ float g_sh[T*H];
// activation planes (hi/lo fp16)
__device__ __half g_h1h[T*H],  g_h1l[T*H];
__device__ __half g_ath[T*H],  g_atl[T*H];
__device__ __half g_xbh[T*H],  g_xbl[T*H];
__device__ __half g_acth[4096*512], g_actl[4096*512];
__device__ __half g_a2h[T*H],  g_a2l[T*H];
// weights: single fp16 plane, ORIGINAL layouts (no transpose)
__device__ __half g_wq[1024*1024], g_wk[512*1024], g_wv[512*1024], g_wo[1024*1024];
__device__ __half g_wsg[1024*1024], g_wsu[1024*1024], g_wsd[1024*1024];
__device__ __half g_weg[(size_t)NE*1024*512], g_weu[(size_t)NE*1024*512];
__device__ __half g_wed[(size_t)NE*512*1024];

// ---------------- asm helpers ----------------
__device__ __forceinline__ void cp16(uint32_t d, const void* s) {
    asm volatile("cp.async.cg.shared.global [%0], [%1], 16;" :: "r"(d), "l"(s));
}
__device__ __forceinline__ void cp_commit() {
    asm volatile("cp.async.commit_group;" ::: "memory");
}
__device__ __forceinline__ void cp_wait1() {
    asm volatile("cp.async.wait_group 1;" ::: "memory");
}
__device__ __forceinline__ void ldmatrix_x4(uint32_t* r, uint32_t a) {
    asm volatile("ldmatrix.sync.aligned.m8n8.x4.shared.b16 {%0,%1,%2,%3}, [%4];"
        : "=r"(r[0]), "=r"(r[1]), "=r"(r[2]), "=r"(r[3]) : "r"(a));
}
__device__ __forceinline__ void ldmatrix_x2(uint32_t* r, uint32_t a) {
    asm volatile("ldmatrix.sync.aligned.m8n8.x2.shared.b16 {%0,%1}, [%2];"
        : "=r"(r[0]), "=r"(r[1]) : "r"(a));
}
__device__ __forceinline__ void ldmatrix_x2_trans(uint32_t* r, uint32_t a) {
    asm volatile("ldmatrix.sync.aligned.m8n8.x2.trans.shared.b16 {%0,%1}, [%2];"
        : "=r"(r[0]), "=r"(r[1]) : "r"(a));
}
__device__ __forceinline__ void mma_f16(float* c, const uint32_t* a, const uint32_t* b) {
    asm volatile("mma.sync.aligned.m16n8k16.row.col.f32.f16.f16.f32 "
        "{%0,%1,%2,%3},{%4,%5,%6,%7},{%8,%9},{%0,%1,%2,%3};"
        : "+f"(c[0]), "+f"(c[1]), "+f"(c[2]), "+f"(c[3])
        : "r"(a[0]), "r"(a[1]), "r"(a[2]), "r"(a[3]), "r"(b[0]), "r"(b[1]));
}

// split fp32 -> fp16 hi/lo (hi+lo carries ~22 mantissa bits)
__device__ __forceinline__ void split1h(float v, __half* h, __half* l) {
    __half hi = __float2half_rn(v);
    *h = hi;
    *l = __float2half_rn(v - __half2float(hi));
}
__device__ __forceinline__ void split4h(__half* hp, __half* lp, float4 f) {
    __half h0 = __float2half_rn(f.x), h1 = __float2half_rn(f.y);
    __half h2 = __float2half_rn(f.z), h3 = __float2half_rn(f.w);
    *(__half2*)(hp)     = __halves2half2(h0, h1);
    *(__half2*)(hp + 2) = __halves2half2(h2, h3);
    *(__half2*)(lp)     = __halves2half2(__float2half_rn(f.x - __half2float(h0)),
                                         __float2half_rn(f.y - __half2float(h1)));
    *(__half2*)(lp + 2) = __halves2half2(__float2half_rn(f.z - __half2float(h2)),
                                         __float2half_rn(f.w - __half2float(h3)));
}

// ---------------- pipelined split-fp16 HMMA GEMM ----------------
// C[M,N] fp32 = (Ah+Al)[M,K] @ op(B)[fp16 1-plane]
// BT=true: B[n][k] (NT). BT=false: B[k][n] (NN). 128x64 CTA tile, k-chunk 32,
// 3-stage cp.async pipeline. GATHER: rows via per-expert token lists.
struct Bseg { const __half* p[4]; int base[4]; };

#define STAGE_BYTES 25600       // A: 2 x 10240 (128x40 halfs), B: <=5120
#define A_BYTES 10240
#define B_OFF 20480
#define NSTAGE 3
#define GEMM_SMEM (STAGE_BYTES*NSTAGE)

template <bool BT, bool GATHER>
__global__ __launch_bounds__(256)
void hgemm(const __half* __restrict__ Ah, const __half* __restrict__ Al, int lda,
           Bseg B, int ldb, size_t estride,
           float* __restrict__ C, int ldc, const float* __restrict__ resid,
           int K, const int* __restrict__ cnt, const int* __restrict__ list, int shift) {
    extern __shared__ __align__(16) char smem[];
    __shared__ int rows_s[128];
    const int tid = threadIdx.x;
    const int lane = tid & 31, wid = tid >> 5;
    const int wm = wid & 3, wn = wid >> 2;     // 4 (m) x 2 (n) warps, 32x32 each
    const int n0 = blockIdx.x * 64;
    const int m0 = blockIdx.y * 128;
    const int e = GATHER ? blockIdx.z : 0;

    if (GATHER) {
        int me = cnt[e];
        if (m0 >= me) return;
        if (tid < 128) rows_s[tid] = (m0 + tid < me) ? list[e * T + m0 + tid] : -1;
    }
    const int sgi = n0 >> 9;
    const __half* Bp = B.p[sgi] + (size_t)e * estride;
    const int nb0 = n0 - B.base[sgi];
    const uint32_t sb = (uint32_t)__cvta_generic_to_shared(smem);
    __syncthreads();

    auto load_stage = [&](int c, int slot) {
        const uint32_t st = sb + slot * STAGE_BYTES;
        const int k0 = c * 32;
#pragma unroll
        for (int i = 0; i < 2; i++) {            // A: 128 rows x 4 x 16B, 2 planes
            int u = tid + i * 256;
            int r = u >> 2, ch = u & 3;
            size_t arow;
            if (GATHER) { int j = rows_s[r]; arow = (size_t)((j < 0) ? 0 : (j >> shift)); }
            else arow = (size_t)(m0 + r);
            uint32_t d = st + r * 80 + ch * 16;
            cp16(d,           Ah + arow * lda + k0 + ch * 8);
            cp16(d + A_BYTES, Al + arow * lda + k0 + ch * 8);
        }
        if (BT) {                                 // B tile 64n x 32k, row stride 40 halfs
            int r = tid >> 2, ch = tid & 3;
            cp16(st + B_OFF + r * 80 + ch * 16,
                 Bp + (size_t)(nb0 + r) * ldb + k0 + ch * 8);
        } else {                                  // B tile 32k x 64n, row stride 72 halfs
            int r = tid >> 3, ch = tid & 7;
            cp16(st + B_OFF + r * 144 + ch * 16,
                 Bp + (size_t)(k0 + r) * ldb + nb0 + ch * 8);
        }
    };

    float acc[2][4][4];
#pragma unroll
    for (int f = 0; f < 2; f++)
#pragma unroll
        for (int j = 0; j < 4; j++)
#pragma unroll
            for (int q = 0; q < 4; q++) acc[f][j][q] = 0.f;

    const int nch = K >> 5;
    load_stage(0, 0); cp_commit();
    load_stage(1, 1); cp_commit();

    for (int c = 0; c < nch; c++) {
        cp_wait1();
        __syncthreads();
        if (c + 2 < nch) load_stage(c + 2, (c + 2) % NSTAGE);
        cp_commit();
        const uint32_t st = sb + (c % NSTAGE) * STAGE_BYTES;
#pragma unroll
        for (int s = 0; s < 2; s++) {
            uint32_t ah[2][4], al[2][4];
#pragma unroll
            for (int f = 0; f < 2; f++) {
                int row = wm * 32 + f * 16 + (lane & 15);
                uint32_t a = st + row * 80 + (s * 16 + (lane >> 4) * 8) * 2;
                ldmatrix_x4(ah[f], a);
                ldmatrix_x4(al[f], a + A_BYTES);
            }
#pragma unroll
            for (int j = 0; j < 4; j++) {
                uint32_t b[2];
                int nb = wn * 32 + j * 8;
                int l = lane & 15;
                if (BT) {
                    int row = nb + (l & 7);
                    int col = s * 16 + ((l >> 3) & 1) * 8;
                    ldmatrix_x2(b, st + B_OFF + row * 80 + col * 2);
                } else {
                    int kk = s * 16 + ((l >> 3) & 1) * 8 + (l & 7);
                    ldmatrix_x2_trans(b, st + B_OFF + kk * 144 + nb * 2);
                }
#pragma unroll
                for (int f = 0; f < 2; f++) {
                    mma_f16(acc[f][j], ah[f], b);
                    mma_f16(acc[f][j], al[f], b);
                }
            }
        }
    }

    // epilogue
#pragma unroll
    for (int f = 0; f < 2; f++) {
        int lr = wm * 32 + f * 16 + (lane >> 2);
#pragma unroll
        for (int j = 0; j < 4; j++) {
            int col = n0 + wn * 32 + j * 8 + (lane & 3) * 2;
            if (GATHER) {
                int j0 = rows_s[lr];
                if (j0 >= 0)
                    *(float2*)(C + (size_t)j0 * ldc + col) =
                        make_float2(acc[f][j][0], acc[f][j][1]);
                int j1 = rows_s[lr + 8];
                if (j1 >= 0)
                    *(float2*)(C + (size_t)j1 * ldc + col) =
                        make_float2(acc[f][j][2], acc[f][j][3]);
            } else {
                int g0 = m0 + lr, g1 = g0 + 8;
                float2 v0 = make_float2(acc[f][j][0], acc[f][j][1]);
                float2 v1 = make_float2(acc[f][j][2], acc[f][j][3]);
                if (resid) {
                    const float* r0 = resid + (size_t)g0 * ldc + col;
                    const float* r1 = resid + (size_t)g1 * ldc + col;
                    v0.x += r0[0]; v0.y += r0[1];
                    v1.x += r1[0]; v1.y += r1[1];
                }
                *(float2*)(C + (size_t)g0 * ldc + col) = v0;
                *(float2*)(C + (size_t)g1 * ldc + col) = v1;
            }
        }
    }
}

// ---------------- conversions ----------------
__global__ void convert_h(const float* __restrict__ s, __half* __restrict__ d, int n4) {
    int i = blockIdx.x * blockDim.x + threadIdx.x;
    if (i >= n4) return;
    float4 f = ((const float4*)s)[i];
    ((__half2*)d)[i * 2]     = __floats2half2_rn(f.x, f.y);
    ((__half2*)d)[i * 2 + 1] = __floats2half2_rn(f.z, f.w);
}

// ---------------- elementwise / norms ----------------
__global__ void rmsnorm_split(const float* __restrict__ x, const float* __restrict__ w,
                              float* __restrict__ outf, __half* __restrict__ oh,
                              __half* __restrict__ ol) {
    int t = blockIdx.x;
    const float* xr = x + (size_t)t * H;
    float s = 0.f;
    for (int i = threadIdx.x; i < H; i += blockDim.x) { float v = xr[i]; s += v * v; }
    __shared__ float red[32];
    for (int o = 16; o; o >>= 1) s += __shfl_xor_sync(0xffffffffu, s, o);
    if ((threadIdx.x & 31) == 0) red[threadIdx.x >> 5] = s;
    __syncthreads();
    if (threadIdx.x < 32) {
        float v = (threadIdx.x < (blockDim.x >> 5)) ? red[threadIdx.x] : 0.f;
        for (int o = 16; o; o >>= 1) v += __shfl_xor_sync(0xffffffffu, v, o);
        if (threadIdx.x == 0) red[0] = v;
    }
    __syncthreads();
    float inv = rsqrtf(red[0] * (1.f / H) + 1e-6f);
    for (int i = threadIdx.x; i < H; i += blockDim.x) {
        float v = xr[i] * inv * w[i];
        if (outf) outf[(size_t)t * H + i] = v;
        split1h(v, &oh[(size_t)t * H + i], &ol[(size_t)t * H + i]);
    }
}

__global__ void silu_split(const float* __restrict__ x, __half* __restrict__ oh,
                           __half* __restrict__ ol, int total, int w, int ldx) {
    int idx = blockIdx.x * blockDim.x + threadIdx.x;
    if (idx >= total) return;
    int r = idx / w, c = idx - r * w;
    float g = x[(size_t)r * ldx + c];
    float u = x[(size_t)r * ldx + w + c];
    float v = g / (1.f + __expf(-g)) * u;
    split1h(v, &oh[idx], &ol[idx]);
}

__global__ void zero_cnt_kernel(int* cnt) { if (threadIdx.x < NE) cnt[threadIdx.x] = 0; }

__global__ void rope_kernel(float* __restrict__ qkv, const int* __restrict__ pos) {
    int t = blockIdx.x;
    int i = threadIdx.x;
    int hh = threadIdx.y;
    float p = (float)pos[t];
    float inv = exp2f(-(float)i * (13.287712379549449f / 64.f));
    float sv, cv;
    sincosf(p * inv, &sv, &cv);
    float* base = (hh < 8) ? (qkv + (size_t)t * 2048 + hh * HD)
                           : (qkv + (size_t)t * 2048 + 1024 + (hh - 8) * HD);
    float x1 = base[i], x2 = base[i + 64];
    base[i]      = x1 * cv - x2 * sv;
    base[i + 64] = x2 * cv + x1 * sv;
}

// ---------------- attention (fp32, split-fp16 output planes) ----------------
__global__ void attn_kernel(const float* __restrict__ qkv, __half* __restrict__ oh,
                            __half* __restrict__ ol) {
    const int h = blockIdx.x;
    const int qt = gridDim.y - 1 - blockIdx.y;
    const int kvh = h >> 1;
    const int warp = threadIdx.x >> 5, lane = threadIdx.x & 31;
    __shared__ float Ks[32][HD];
    __shared__ float Vs[32][HD];
    const int q0 = qt * 32 + warp * 4;
    float qr[4][4];
#pragma unroll
    for (int i = 0; i < 4; i++) {
        float4 f = *(const float4*)(qkv + (size_t)(q0 + i) * 2048 + h * HD + lane * 4);
        qr[i][0] = f.x; qr[i][1] = f.y; qr[i][2] = f.z; qr[i][3] = f.w;
    }
    float acc[4][4] = {};
    float mx[4] = {-1e30f, -1e30f, -1e30f, -1e30f};
    float ls[4] = {0.f, 0.f, 0.f, 0.f};
    const float scale = 0.088388347648318447f;
    for (int kt = 0; kt <= qt; kt++) {
        __syncthreads();
        for (int r = warp; r < 32; r += 8) {
            int kr = kt * 32 + r;
            *(float4*)&Ks[r][lane * 4] =
                *(const float4*)(qkv + (size_t)kr * 2048 + 1024 + kvh * HD + lane * 4);
            *(float4*)&Vs[r][lane * 4] =
                *(const float4*)(qkv + (size_t)kr * 2048 + 1536 + kvh * HD + lane * 4);
        }
        __syncthreads();
        const bool diag = (kt == qt);
        for (int j = 0; j < 32; j++) {
            const int kg = kt * 32 + j;
            float kv0 = Ks[j][lane*4+0], kv1 = Ks[j][lane*4+1];
            float kv2 = Ks[j][lane*4+2], kv3 = Ks[j][lane*4+3];
            float4 vv = *(const float4*)&Vs[j][lane * 4];
#pragma unroll
            for (int i = 0; i < 4; i++) {
                if (diag && kg > q0 + i) continue;
                float p = qr[i][0]*kv0 + qr[i][1]*kv1 + qr[i][2]*kv2 + qr[i][3]*kv3;
                p += __shfl_xor_sync(0xffffffffu, p, 16);
                p += __shfl_xor_sync(0xffffffffu, p, 8);
                p += __shfl_xor_sync(0xffffffffu, p, 4);
                p += __shfl_xor_sync(0xffffffffu, p, 2);
                p += __shfl_xor_sync(0xffffffffu, p, 1);
                float sc = p * scale;
                if (sc > mx[i]) {
                    float cc = __expf(mx[i] - sc);
                    ls[i] = ls[i] * cc + 1.f;
                    acc[i][0] = acc[i][0]*cc + vv.x; acc[i][1] = acc[i][1]*cc + vv.y;
                    acc[i][2] = acc[i][2]*cc + vv.z; acc[i][3] = acc[i][3]*cc + vv.w;
                    mx[i] = sc;
                } else {
                    float ee = __expf(sc - mx[i]);
                    ls[i] += ee;
                    acc[i][0] += ee*vv.x; acc[i][1] += ee*vv.y;
                    acc[i][2] += ee*vv.z; acc[i][3] += ee*vv.w;
                }
            }
        }
    }
#pragma unroll
    for (int i = 0; i < 4; i++) {
        float inv = 1.f / ls[i];
        float4 o = make_float4(acc[i][0]*inv, acc[i][1]*inv, acc[i][2]*inv, acc[i][3]*inv);
        size_t off = (size_t)(q0 + i) * H + h * HD + lane * 4;
        split4h(oh + off, ol + off, o);
    }
}

// ---------------- router ----------------
__global__ void router_gemm(const float* __restrict__ xb, const float* __restrict__ rw,
                            float* __restrict__ logits) {
    __shared__ float xr[H];
    int t = blockIdx.x;
    for (int i = threadIdx.x; i < H; i += 128) xr[i] = xb[(size_t)t * H + i];
    __syncthreads();
    int w = threadIdx.x >> 5, lane = threadIdx.x & 31;
    for (int e8 = 0; e8 < 8; e8++) {
        int e = w * 8 + e8;
        const float* wr = rw + (size_t)e * H;
        float s = 0.f;
        for (int k = lane; k < H; k += 32) s += xr[k] * wr[k];
        for (int o = 16; o; o >>= 1) s += __shfl_xor_sync(0xffffffffu, s, o);
        if (lane == 0) logits[t * NE + e] = s;
    }
}

__global__ void router_kernel(const float* __restrict__ logits, const float* __restrict__ bias,
                              float* __restrict__ topkw, int* __restrict__ cnt,
                              int* __restrict__ list) {
    int t = blockIdx.x * blockDim.x + threadIdx.x;
    if (t >= T) return;
    float sc[NE], sfc[NE];
#pragma unroll
    for (int e = 0; e < NE; e++) {
        float l = logits[t * NE + e];
        float s = 1.f / (1.f + __expf(-l));
        sc[e] = s; sfc[e] = s + bias[e];
    }
    float gs[8];
#pragma unroll
    for (int g = 0; g < 8; g++) {
        float v[4] = {sfc[g*4+0], sfc[g*4+1], sfc[g*4+2], sfc[g*4+3]};
        float sum = v[0] + v[1] + v[2] + v[3];
        int mi = 0;
        for (int i = 1; i < 4; i++) if (v[i] < v[mi]) mi = i;
        float m2 = 1e30f;
        for (int i = 0; i < 4; i++) if (i != mi && v[i] < m2) m2 = v[i];
        gs[g] = sum - v[mi] - m2;
    }
    bool gsel[8] = {};
    for (int r = 0; r < 4; r++) {
        float best = -1e30f; int bi = 0;
        for (int g = 0; g < 8; g++) if (!gsel[g] && gs[g] > best) { best = gs[g]; bi = g; }
        gsel[bi] = true;
    }
    float masked[NE];
#pragma unroll
    for (int e = 0; e < NE; e++) masked[e] = gsel[e >> 2] ? sfc[e] : 0.f;
    int idxs[4]; float ws[4]; float wsum = 0.f;
    for (int r = 0; r < 4; r++) {
        float best = -1e30f; int bi = 0;
        for (int e = 0; e < NE; e++) if (masked[e] > best) { best = masked[e]; bi = e; }
        masked[bi] = -1e30f;
        idxs[r] = bi; ws[r] = sc[bi]; wsum += ws[r];
    }
    float inv = 2.5f / (wsum + 1e-20f);
    for (int r = 0; r < 4; r++) {
        topkw[t * 4 + r] = ws[r] * inv;
        int pos = atomicAdd(&cnt[idxs[r]], 1);
        list[idxs[r] * T + pos] = t * 4 + r;
    }
}

__global__ void final_kernel(const float* __restrict__ h2, const float* __restrict__ sh,
                             const float* __restrict__ ed, const float* __restrict__ tw,
                             float* __restrict__ out) {
    int idx = blockIdx.x * blockDim.x + threadIdx.x;
    if (idx >= T * H) return;
    int t = idx >> 10;
    int hh = idx & 1023;
    float r = h2[idx] + sh[idx];
#pragma unroll
    for (int kk = 0; kk < 4; kk++)
        r += tw[t * 4 + kk] * ed[(size_t)(t * 4 + kk) * H + hh];
    out[idx] = r;
}

// ---------------- host ----------------
extern "C" void kernel_launch(void* const* d_in, const int* in_sizes, int n_in,
                              void* d_out, int out_size) {
    (void)in_sizes; (void)n_in; (void)out_size;
    const float* hidden   = (const float*)d_in[0];
    const int*   pos      = (const int*)d_in[1];
    const float* ln1_w    = (const float*)d_in[2];
    const float* ln2_w    = (const float*)d_in[3];
    const float* q_w      = (const float*)d_in[4];
    const float* k_w      = (const float*)d_in[5];
    const float* v_w      = (const float*)d_in[6];
    const float* o_w      = (const float*)d_in[7];
    const float* router_w = (const float*)d_in[8];
    const float* r_bias   = (const float*)d_in[9];
    const float* eg_w     = (const float*)d_in[10];
    const float* eu_w     = (const float*)d_in[11];
    const float* ed_w     = (const float*)d_in[12];
    const float* sg_w     = (const float*)d_in[13];
    const float* su_w     = (const float*)d_in[14];
    const float* sd_w     = (const float*)d_in[15];
    float* out = (float*)d_out;

#define GSYM(p, s) cudaGetSymbolAddress((void**)&p, s)
    float *qkv, *h2, *xb, *logits, *topkw, *egu, *edb, *sgu, *sh;
    int *cnt, *list;
    __half *h1h,*h1l,*ath,*atl,*xbh,*xbl,*acth,*actl,*a2h,*a2l;
    __half *wq,*wk,*wv,*wo,*wsg,*wsu,*wsd,*weg,*weu,*wed;
    GSYM(qkv,g_qkv); GSYM(h2,g_h2); GSYM(xb,g_xb);
    GSYM(logits,g_logits); GSYM(topkw,g_topkw); GSYM(cnt,g_cnt); GSYM(list,g_list);
    GSYM(egu,g_egu); GSYM(edb,g_edb); GSYM(sgu,g_sgu); GSYM(sh,g_sh);
    GSYM(h1h,g_h1h); GSYM(h1l,g_h1l); GSYM(ath,g_ath); GSYM(atl,g_atl);
    GSYM(xbh,g_xbh); GSYM(xbl,g_xbl); GSYM(acth,g_acth); GSYM(actl,g_actl);
    GSYM(a2h,g_a2h); GSYM(a2l,g_a2l);
    GSYM(wq,g_wq); GSYM(wk,g_wk); GSYM(wv,g_wv); GSYM(wo,g_wo);
    GSYM(wsg,g_wsg); GSYM(wsu,g_wsu); GSYM(wsd,g_wsd);
    GSYM(weg,g_weg); GSYM(weu,g_weu); GSYM(wed,g_wed);
#undef GSYM

    cudaFuncSetAttribute(hgemm<true,false>,  cudaFuncAttributeMaxDynamicSharedMemorySize, GEMM_SMEM);
    cudaFuncSetAttribute(hgemm<false,false>, cudaFuncAttributeMaxDynamicSharedMemorySize, GEMM_SMEM);
    cudaFuncSetAttribute(hgemm<false,true>,  cudaFuncAttributeMaxDynamicSharedMemorySize, GEMM_SMEM);

    zero_cnt_kernel<<<1, 32>>>(cnt);

    // ---- weight conversion (fp16, original layouts) ----
    convert_h<<<1024, 256>>>(q_w, wq, 262144);
    convert_h<<<512,  256>>>(k_w, wk, 131072);
    convert_h<<<512,  256>>>(v_w, wv, 131072);
    convert_h<<<1024, 256>>>(o_w, wo, 262144);
    convert_h<<<1024, 256>>>(sg_w, wsg, 262144);
    convert_h<<<1024, 256>>>(su_w, wsu, 262144);
    convert_h<<<1024, 256>>>(sd_w, wsd, 262144);
    convert_h<<<16384, 256>>>(eg_w, weg, 4194304);
    convert_h<<<16384, 256>>>(eu_w, weu, 4194304);
    convert_h<<<16384, 256>>>(ed_w, wed, 4194304);

    // ---- attention branch ----
    rmsnorm_split<<<T, 256>>>(hidden, ln1_w, nullptr, h1h, h1l);
    {   // fused QKV (NT): N=2048 = q|k|v
        Bseg b = {{wq, wq, wk, wv}, {0, 0, 1024, 1536}};
        hgemm<true,false><<<dim3(32, 8), 256, GEMM_SMEM>>>(
            h1h, h1l, 1024, b, 1024, 0, qkv, 2048, nullptr, 1024, nullptr, nullptr, 0);
    }
    rope_kernel<<<T, dim3(64, 12)>>>(qkv, pos);
    attn_kernel<<<dim3(NH, T / 32), 256>>>(qkv, ath, atl);
    {   // O projection (NT) + residual -> h2
        Bseg b = {{wo, wo, wo, wo}, {0, 0, 0, 0}};
        hgemm<true,false><<<dim3(16, 8), 256, GEMM_SMEM>>>(
            ath, atl, 1024, b, 1024, 0, h2, 1024, hidden, 1024, nullptr, nullptr, 0);
    }

    // ---- MoE branch ----
    rmsnorm_split<<<T, 256>>>(h2, ln2_w, xb, xbh, xbl);
    router_gemm<<<T, 128>>>(xb, router_w, logits);
    router_kernel<<<(T + 255) / 256, 256>>>(logits, r_bias, topkw, cnt, list);

    {   // routed experts up: fused eg|eu (NN, gather)
        Bseg b = {{weg, weu, weg, weu}, {0, 512, 0, 512}};
        hgemm<false,true><<<dim3(16, 8, NE), 256, GEMM_SMEM>>>(
            xbh, xbl, 1024, b, 512, (size_t)1024*512, egu, 1024, nullptr, 1024, cnt, list, 2);
    }
    silu_split<<<(4096 * 512 + 255) / 256, 256>>>(egu, acth, actl, 4096 * 512, 512, 1024);
    {   // expert down (NN, gather)
        Bseg b = {{wed, wed, wed, wed}, {0, 0, 0, 0}};
        hgemm<false,true><<<dim3(16, 8, NE), 256, GEMM_SMEM>>>(
            acth, actl, 512, b, 1024, (size_t)512*1024, edb, 1024, nullptr, 512, cnt, list, 0);
    }

    {   // shared expert up: fused sg|su (NN)
        Bseg b = {{wsg, wsg, wsu, wsu}, {0, 0, 1024, 1024}};
        hgemm<false,false><<<dim3(32, 8), 256, GEMM_SMEM>>>(
            xbh, xbl, 1024, b, 1024, 0, sgu, 2048, nullptr, 1024, nullptr, nullptr, 0);
    }
    silu_split<<<(T * SI + 255) / 256, 256>>>(sgu, a2h, a2l, T * SI, 1024, 2048);
    {   // shared down (NN)
        Bseg b = {{wsd, wsd, wsd, wsd}, {0, 0, 0, 0}};
        hgemm<false,false><<<dim3(16, 8), 256, GEMM_SMEM>>>(
            a2h, a2l, 1024, b, 1024, 0, sh, 1024, nullptr, 1024, nullptr, nullptr, 0);
    }

    final_kernel<<<(T * H + 255) / 256, 256>>>(h2, sh, edb, topkw, out);
}

// round 5
// speedup vs baseline: 1.1384x; 1.1384x over previous
#include <cuda_runtime.h>
#include <math.h>
#include <stdint.h>

#define T 1024
#define H 1024
#define NH 8
#define NKV 4
#define HD 128
#define NE 32
#define MI 512
#define SI 1024

// ---------------- scratch (all fp32 now) ----------------
__device__ float g_h1[T*H];
__device__ float g_qkv[T*2048];
__device__ float g_at[T*H];
__device__ float g_h2[T*H];
__device__ float g_xb[T*H];
__device__ float g_logits[T*NE];
__device__ float g_topkw[T*4];
__device__ int   g_cnt[NE];
__device__ int   g_list[NE*T];
__device__ float g_egu[4096*1024];
__device__ float g_act[4096*512];
__device__ float g_edb[4096*1024];
__device__ float g_sgu[T*2048];
__device__ float g_act2[T*SI];
__device__ float g_sh[T*H];
// K-major transposed weight copies (fp32)
__device__ float g_sgT[1024*1024];
__device__ float g_suT[1024*1024];
__device__ float g_sdT[1024*1024];
__device__ float g_egT[(size_t)NE*512*1024];
__device__ float g_euT[(size_t)NE*512*1024];
__device__ float g_edT[(size_t)NE*1024*512];

// ---------------- asm helpers ----------------
__device__ __forceinline__ void cp16(uint32_t d, const void* s) {
    asm volatile("cp.async.cg.shared.global [%0], [%1], 16;" :: "r"(d), "l"(s));
}
__device__ __forceinline__ void cp_commit() {
    asm volatile("cp.async.commit_group;" ::: "memory");
}
__device__ __forceinline__ void cp_wait1() {
    asm volatile("cp.async.wait_group 1;" ::: "memory");
}
__device__ __forceinline__ void cp_wait0() {
    asm volatile("cp.async.wait_group 0;" ::: "memory");
}
// packed fp32x2 FMA: c = a*b + c elementwise on {lo,hi}
__device__ __forceinline__ void fma2(unsigned long long& c, unsigned long long a,
                                     unsigned long long b) {
    asm("fma.rn.f32x2 %0, %1, %2, %0;" : "+l"(c) : "l"(a), "l"(b));
}
union U64F2 { unsigned long long u; float2 f; };

// ---------------- packed-fp32 GEMM ----------------
// C[M,N] = A[M,K] @ B^T, all fp32, B is [N][K] K-major. CTA tile 128x64,
// thread microtile 8x4, k-pair accumulation via fma.rn.f32x2.
// GATHER: A rows / C rows via per-expert token lists.
struct Bseg { const float* p[4]; int base[4]; };

#define AS_F 4608                 // 128 rows x 36 floats
#define BS_F 2304                 // 64 rows x 36 floats
#define GEMM_SMEM ((AS_F + BS_F) * 2 * 4)

template <bool GATHER>
__global__ __launch_bounds__(256)
void fgemm(const float* __restrict__ A, int lda, Bseg B, int ldb, size_t estride,
           float* __restrict__ C, int ldc, const float* __restrict__ resid,
           int K, const int* __restrict__ cnt, const int* __restrict__ list, int shift) {
    extern __shared__ __align__(16) float smemf[];
    __shared__ int rows_s[128];
    const int tid = threadIdx.x;
    const int tx = tid & 15, ty = tid >> 4;
    const int n0 = blockIdx.x * 64;
    const int m0 = blockIdx.y * 128;
    const int e = GATHER ? blockIdx.z : 0;

    if (GATHER) {
        int me = cnt[e];
        if (m0 >= me) return;
        if (tid < 128) rows_s[tid] = (m0 + tid < me) ? list[e * T + m0 + tid] : -1;
        __syncthreads();
    }
    const int sgi = n0 >> 9;
    const float* Bp = B.p[sgi] + (size_t)e * estride;
    const int nb0 = n0 - B.base[sgi];
    const uint32_t sb = (uint32_t)__cvta_generic_to_shared(smemf);

    auto load_stage = [&](int cc, int slot) {
        const int k0 = cc * 32;
        const uint32_t sA = sb + slot * (AS_F * 4);
        const uint32_t sB = sb + (2 * AS_F + slot * BS_F) * 4;
#pragma unroll
        for (int it = 0; it < 4; it++) {          // A: 128 rows x 8 x 16B
            int idx = tid + it * 256;
            int r = idx >> 3, ch = idx & 7;
            size_t arow;
            if (GATHER) { int j = rows_s[r]; arow = (j < 0) ? 0 : (size_t)(j >> shift); }
            else arow = (size_t)(m0 + r);
            cp16(sA + r * 144 + ch * 16, A + arow * lda + k0 + ch * 4);
        }
#pragma unroll
        for (int it = 0; it < 2; it++) {          // B: 64 rows x 8 x 16B
            int idx = tid + it * 256;
            int r = idx >> 3, ch = idx & 7;
            cp16(sB + r * 144 + ch * 16, Bp + (size_t)(nb0 + r) * ldb + k0 + ch * 4);
        }
    };

    unsigned long long acc[8][4];
#pragma unroll
    for (int i = 0; i < 8; i++)
#pragma unroll
        for (int j = 0; j < 4; j++) acc[i][j] = 0ull;

    const int nch = K >> 5;
    load_stage(0, 0); cp_commit();
    load_stage(1, 1); cp_commit();

    for (int c = 0; c < nch; c++) {
        if (c + 2 < nch) cp_wait1(); else cp_wait0();
        __syncthreads();
        const int slot = c & 1;
        const float* Ab = smemf + slot * AS_F;
        const float* Bb = smemf + 2 * AS_F + slot * BS_F;
#pragma unroll
        for (int kq = 0; kq < 8; kq++) {
            ulonglong2 bv[4];
#pragma unroll
            for (int j = 0; j < 4; j++)
                bv[j] = *(const ulonglong2*)&Bb[(j * 16 + tx) * 36 + kq * 4];
#pragma unroll
            for (int i = 0; i < 8; i++) {
                ulonglong2 av = *(const ulonglong2*)&Ab[(ty * 8 + i) * 36 + kq * 4];
#pragma unroll
                for (int j = 0; j < 4; j++) {
                    fma2(acc[i][j], av.x, bv[j].x);
                    fma2(acc[i][j], av.y, bv[j].y);
                }
            }
        }
        __syncthreads();
        if (c + 2 < nch) { load_stage(c + 2, slot); cp_commit(); }
    }

    // epilogue: fold k-pairs, store
#pragma unroll
    for (int i = 0; i < 8; i++) {
        int lr = ty * 8 + i;
        float* crow;
        if (GATHER) {
            int jj = rows_s[lr];
            if (jj < 0) continue;
            crow = C + (size_t)jj * ldc;
        } else {
            crow = C + (size_t)(m0 + lr) * ldc;
        }
#pragma unroll
        for (int j = 0; j < 4; j++) {
            U64F2 u; u.u = acc[i][j];
            float v = u.f.x + u.f.y;
            int col = n0 + j * 16 + tx;
            if (!GATHER && resid) v += resid[(size_t)(m0 + lr) * ldc + col];
            crow[col] = v;
        }
    }
}

// ---------------- weight transpose: src [K][N] -> dst [N][K] (fp32) ----------------
__global__ void transpose_w(const float* __restrict__ src, float* __restrict__ dst,
                            int K, int N, size_t sstride, size_t dstride) {
    __shared__ float tile[32][33];
    int e = blockIdx.z;
    const float* sp = src + (size_t)e * sstride;
    float* dp = dst + (size_t)e * dstride;
    int k0 = blockIdx.y * 32, n0 = blockIdx.x * 32;
    int tx = threadIdx.x, ty = threadIdx.y;   // 32 x 8
#pragma unroll
    for (int i = 0; i < 4; i++)
        tile[ty + i * 8][tx] = sp[(size_t)(k0 + ty + i * 8) * N + n0 + tx];
    __syncthreads();
#pragma unroll
    for (int i = 0; i < 4; i++)
        dp[(size_t)(n0 + ty + i * 8) * K + k0 + tx] = tile[tx][ty + i * 8];
}

// ---------------- elementwise / norms ----------------
__global__ void rmsnorm_kernel(const float* __restrict__ x, const float* __restrict__ w,
                               float* __restrict__ out) {
    int t = blockIdx.x;
    const float* xr = x + (size_t)t * H;
    float s = 0.f;
    for (int i = threadIdx.x; i < H; i += blockDim.x) { float v = xr[i]; s += v * v; }
    __shared__ float red[32];
    for (int o = 16; o; o >>= 1) s += __shfl_xor_sync(0xffffffffu, s, o);
    if ((threadIdx.x & 31) == 0) red[threadIdx.x >> 5] = s;
    __syncthreads();
    if (threadIdx.x < 32) {
        float v = (threadIdx.x < (blockDim.x >> 5)) ? red[threadIdx.x] : 0.f;
        for (int o = 16; o; o >>= 1) v += __shfl_xor_sync(0xffffffffu, v, o);
        if (threadIdx.x == 0) red[0] = v;
    }
    __syncthreads();
    float inv = rsqrtf(red[0] * (1.f / H) + 1e-6f);
    for (int i = threadIdx.x; i < H; i += blockDim.x)
        out[(size_t)t * H + i] = xr[i] * inv * w[i];
}

__global__ void silu_pair_kernel(const float* __restrict__ x, float* __restrict__ o,
                                 int total, int w, int ldx) {
    int idx = blockIdx.x * blockDim.x + threadIdx.x;
    if (idx >= total) return;
    int r = idx / w, c = idx - r * w;
    float g = x[(size_t)r * ldx + c];
    float u = x[(size_t)r * ldx + w + c];
    o[idx] = g / (1.f + __expf(-g)) * u;
}

__global__ void zero_cnt_kernel(int* cnt) { if (threadIdx.x < NE) cnt[threadIdx.x] = 0; }

__global__ void rope_kernel(float* __restrict__ qkv, const int* __restrict__ pos) {
    int t = blockIdx.x;
    int i = threadIdx.x;
    int hh = threadIdx.y;
    float p = (float)pos[t];
    float inv = exp2f(-(float)i * (13.287712379549449f / 64.f));
    float sv, cv;
    sincosf(p * inv, &sv, &cv);
    float* base = (hh < 8) ? (qkv + (size_t)t * 2048 + hh * HD)
                           : (qkv + (size_t)t * 2048 + 1024 + (hh - 8) * HD);
    float x1 = base[i], x2 = base[i + 64];
    base[i]      = x1 * cv - x2 * sv;
    base[i + 64] = x2 * cv + x1 * sv;
}

// ---------------- causal flash attention (fp32) ----------------
__global__ void attn_kernel(const float* __restrict__ qkv, float* __restrict__ out) {
    const int h = blockIdx.x;
    const int qt = gridDim.y - 1 - blockIdx.y;
    const int kvh = h >> 1;
    const int warp = threadIdx.x >> 5, lane = threadIdx.x & 31;
    __shared__ float Ks[32][HD];
    __shared__ float Vs[32][HD];
    const int q0 = qt * 32 + warp * 4;
    float qr[4][4];
#pragma unroll
    for (int i = 0; i < 4; i++) {
        float4 f = *(const float4*)(qkv + (size_t)(q0 + i) * 2048 + h * HD + lane * 4);
        qr[i][0] = f.x; qr[i][1] = f.y; qr[i][2] = f.z; qr[i][3] = f.w;
    }
    float acc[4][4] = {};
    float mx[4] = {-1e30f, -1e30f, -1e30f, -1e30f};
    float ls[4] = {0.f, 0.f, 0.f, 0.f};
    const float scale = 0.088388347648318447f;
    for (int kt = 0; kt <= qt; kt++) {
        __syncthreads();
        for (int r = warp; r < 32; r += 8) {
            int kr = kt * 32 + r;
            *(float4*)&Ks[r][lane * 4] =
                *(const float4*)(qkv + (size_t)kr * 2048 + 1024 + kvh * HD + lane * 4);
            *(float4*)&Vs[r][lane * 4] =
                *(const float4*)(qkv + (size_t)kr * 2048 + 1536 + kvh * HD + lane * 4);
        }
        __syncthreads();
        const bool diag = (kt == qt);
        for (int j = 0; j < 32; j++) {
            const int kg = kt * 32 + j;
            float kv0 = Ks[j][lane*4+0], kv1 = Ks[j][lane*4+1];
            float kv2 = Ks[j][lane*4+2], kv3 = Ks[j][lane*4+3];
            float4 vv = *(const float4*)&Vs[j][lane * 4];
#pragma unroll
            for (int i = 0; i < 4; i++) {
                if (diag && kg > q0 + i) continue;
                float p = qr[i][0]*kv0 + qr[i][1]*kv1 + qr[i][2]*kv2 + qr[i][3]*kv3;
                p += __shfl_xor_sync(0xffffffffu, p, 16);
                p += __shfl_xor_sync(0xffffffffu, p, 8);
                p += __shfl_xor_sync(0xffffffffu, p, 4);
                p += __shfl_xor_sync(0xffffffffu, p, 2);
                p += __shfl_xor_sync(0xffffffffu, p, 1);
                float sc = p * scale;
                if (sc > mx[i]) {
                    float cc = __expf(mx[i] - sc);
                    ls[i] = ls[i] * cc + 1.f;
                    acc[i][0] = acc[i][0]*cc + vv.x; acc[i][1] = acc[i][1]*cc + vv.y;
                    acc[i][2] = acc[i][2]*cc + vv.z; acc[i][3] = acc[i][3]*cc + vv.w;
                    mx[i] = sc;
                } else {
                    float ee = __expf(sc - mx[i]);
                    ls[i] += ee;
                    acc[i][0] += ee*vv.x; acc[i][1] += ee*vv.y;
                    acc[i][2] += ee*vv.z; acc[i][3] += ee*vv.w;
                }
            }
        }
    }
#pragma unroll
    for (int i = 0; i < 4; i++) {
        float inv = 1.f / ls[i];
        float4 o = make_float4(acc[i][0]*inv, acc[i][1]*inv, acc[i][2]*inv, acc[i][3]*inv);
        *(float4*)(out + (size_t)(q0 + i) * H + h * HD + lane * 4) = o;
    }
}

// ---------------- router ----------------
__global__ void router_gemm(const float* __restrict__ xb, const float* __restrict__ rw,
                            float* __restrict__ logits) {
    __shared__ float xr[H];
    int t = blockIdx.x;
    for (int i = threadIdx.x; i < H; i += 128) xr[i] = xb[(size_t)t * H + i];
    __syncthreads();
    int w = threadIdx.x >> 5, lane = threadIdx.x & 31;
    for (int e8 = 0; e8 < 8; e8++) {
        int e = w * 8 + e8;
        const float* wr = rw + (size_t)e * H;
        float s = 0.f;
        for (int k = lane; k < H; k += 32) s += xr[k] * wr[k];
        for (int o = 16; o; o >>= 1) s += __shfl_xor_sync(0xffffffffu, s, o);
        if (lane == 0) logits[t * NE + e] = s;
    }
}

__global__ void router_kernel(const float* __restrict__ logits, const float* __restrict__ bias,
                              float* __restrict__ topkw, int* __restrict__ cnt,
                              int* __restrict__ list) {
    int t = blockIdx.x * blockDim.x + threadIdx.x;
    if (t >= T) return;
    float sc[NE], sfc[NE];
#pragma unroll
    for (int e = 0; e < NE; e++) {
        float l = logits[t * NE + e];
        float s = 1.f / (1.f + __expf(-l));
        sc[e] = s; sfc[e] = s + bias[e];
    }
    float gs[8];
#pragma unroll
    for (int g = 0; g < 8; g++) {
        float v[4] = {sfc[g*4+0], sfc[g*4+1], sfc[g*4+2], sfc[g*4+3]};
        float sum = v[0] + v[1] + v[2] + v[3];
        int mi = 0;
        for (int i = 1; i < 4; i++) if (v[i] < v[mi]) mi = i;
        float m2 = 1e30f;
        for (int i = 0; i < 4; i++) if (i != mi && v[i] < m2) m2 = v[i];
        gs[g] = sum - v[mi] - m2;
    }
    bool gsel[8] = {};
    for (int r = 0; r < 4; r++) {
        float best = -1e30f; int bi = 0;
        for (int g = 0; g < 8; g++) if (!gsel[g] && gs[g] > best) { best = gs[g]; bi = g; }
        gsel[bi] = true;
    }
    float masked[NE];
#pragma unroll
    for (int e = 0; e < NE; e++) masked[e] = gsel[e >> 2] ? sfc[e] : 0.f;
    int idxs[4]; float ws[4]; float wsum = 0.f;
    for (int r = 0; r < 4; r++) {
        float best = -1e30f; int bi = 0;
        for (int e = 0; e < NE; e++) if (masked[e] > best) { best = masked[e]; bi = e; }
        masked[bi] = -1e30f;
        idxs[r] = bi; ws[r] = sc[bi]; wsum += ws[r];
    }
    float inv = 2.5f / (wsum + 1e-20f);
    for (int r = 0; r < 4; r++) {
        topkw[t * 4 + r] = ws[r] * inv;
        int pos = atomicAdd(&cnt[idxs[r]], 1);
        list[idxs[r] * T + pos] = t * 4 + r;
    }
}

__global__ void final_kernel(const float* __restrict__ h2, const float* __restrict__ sh,
                             const float* __restrict__ ed, const float* __restrict__ tw,
                             float* __restrict__ out) {
    int idx = blockIdx.x * blockDim.x + threadIdx.x;
    if (idx >= T * H) return;
    int t = idx >> 10;
    int hh = idx & 1023;
    float r = h2[idx] + sh[idx];
#pragma unroll
    for (int kk = 0; kk < 4; kk++)
        r += tw[t * 4 + kk] * ed[(size_t)(t * 4 + kk) * H + hh];
    out[idx] = r;
}

// ---------------- host ----------------
extern "C" void kernel_launch(void* const* d_in, const int* in_sizes, int n_in,
                              void* d_out, int out_size) {
    (void)in_sizes; (void)n_in; (void)out_size;
    const float* hidden   = (const float*)d_in[0];
    const int*   pos      = (const int*)d_in[1];
    const float* ln1_w    = (const float*)d_in[2];
    const float* ln2_w    = (const float*)d_in[3];
    const float* q_w      = (const float*)d_in[4];
    const float* k_w      = (const float*)d_in[5];
    const float* v_w      = (const float*)d_in[6];
    const float* o_w      = (const float*)d_in[7];
    const float* router_w = (const float*)d_in[8];
    const float* r_bias   = (const float*)d_in[9];
    const float* eg_w     = (const float*)d_in[10];
    const float* eu_w     = (const float*)d_in[11];
    const float* ed_w     = (const float*)d_in[12];
    const float* sg_w     = (const float*)d_in[13];
    const float* su_w     = (const float*)d_in[14];
    const float* sd_w     = (const float*)d_in[15];
    float* out = (float*)d_out;

#define GSYM(p, s) cudaGetSymbolAddress((void**)&p, s)
    float *h1, *qkv, *at, *h2, *xb, *logits, *topkw, *egu, *act, *edb, *sgu, *act2, *sh;
    float *sgT, *suT, *sdT, *egT, *euT, *edT;
    int *cnt, *list;
    GSYM(h1,g_h1); GSYM(qkv,g_qkv); GSYM(at,g_at); GSYM(h2,g_h2); GSYM(xb,g_xb);
    GSYM(logits,g_logits); GSYM(topkw,g_topkw); GSYM(cnt,g_cnt); GSYM(list,g_list);
    GSYM(egu,g_egu); GSYM(act,g_act); GSYM(edb,g_edb);
    GSYM(sgu,g_sgu); GSYM(act2,g_act2); GSYM(sh,g_sh);
    GSYM(sgT,g_sgT); GSYM(suT,g_suT); GSYM(sdT,g_sdT);
    GSYM(egT,g_egT); GSYM(euT,g_euT); GSYM(edT,g_edT);
#undef GSYM

    cudaFuncSetAttribute(fgemm<false>, cudaFuncAttributeMaxDynamicSharedMemorySize, GEMM_SMEM);
    cudaFuncSetAttribute(fgemm<true>,  cudaFuncAttributeMaxDynamicSharedMemorySize, GEMM_SMEM);

    zero_cnt_kernel<<<1, 32>>>(cnt);

    // ---- one-time weight transposes to K-major ----
    transpose_w<<<dim3(32, 32, 1), dim3(32, 8)>>>(sg_w, sgT, 1024, 1024, 0, 0);
    transpose_w<<<dim3(32, 32, 1), dim3(32, 8)>>>(su_w, suT, 1024, 1024, 0, 0);
    transpose_w<<<dim3(32, 32, 1), dim3(32, 8)>>>(sd_w, sdT, 1024, 1024, 0, 0);
    transpose_w<<<dim3(16, 32, NE), dim3(32, 8)>>>(eg_w, egT, 1024, 512,
                                                   (size_t)1024*512, (size_t)512*1024);
    transpose_w<<<dim3(16, 32, NE), dim3(32, 8)>>>(eu_w, euT, 1024, 512,
                                                   (size_t)1024*512, (size_t)512*1024);
    transpose_w<<<dim3(32, 16, NE), dim3(32, 8)>>>(ed_w, edT, 512, 1024,
                                                   (size_t)512*1024, (size_t)1024*512);

    // ---- attention branch ----
    rmsnorm_kernel<<<T, 256>>>(hidden, ln1_w, h1);
    {   // fused QKV (weights already [N][K] K-major — native NT)
        Bseg b = {{q_w, q_w, k_w, v_w}, {0, 0, 1024, 1536}};
        fgemm<false><<<dim3(32, 8), 256, GEMM_SMEM>>>(
            h1, 1024, b, 1024, 0, qkv, 2048, nullptr, 1024, nullptr, nullptr, 0);
    }
    rope_kernel<<<T, dim3(64, 12)>>>(qkv, pos);
    attn_kernel<<<dim3(NH, T / 32), 256>>>(qkv, at);
    {   // O projection + residual
        Bseg b = {{o_w, o_w, o_w, o_w}, {0, 0, 0, 0}};
        fgemm<false><<<dim3(16, 8), 256, GEMM_SMEM>>>(
            at, 1024, b, 1024, 0, h2, 1024, hidden, 1024, nullptr, nullptr, 0);
    }

    // ---- MoE branch ----
    rmsnorm_kernel<<<T, 256>>>(h2, ln2_w, xb);
    router_gemm<<<T, 128>>>(xb, router_w, logits);
    router_kernel<<<(T + 255) / 256, 256>>>(logits, r_bias, topkw, cnt, list);

    {   // routed experts up: fused eg|eu (gather)
        Bseg b = {{egT, euT, egT, euT}, {0, 512, 0, 512}};
        fgemm<true><<<dim3(16, 8, NE), 256, GEMM_SMEM>>>(
            xb, 1024, b, 1024, (size_t)512*1024, egu, 1024, nullptr, 1024, cnt, list, 2);
    }
    silu_pair_kernel<<<(4096 * 512 + 255) / 256, 256>>>(egu, act, 4096 * 512, 512, 1024);
    {   // expert down (gather)
        Bseg b = {{edT, edT, edT, edT}, {0, 0, 0, 0}};
        fgemm<true><<<dim3(16, 8, NE), 256, GEMM_SMEM>>>(
            act, 512, b, 512, (size_t)1024*512, edb, 1024, nullptr, 512, cnt, list, 0);
    }

    {   // shared expert up: fused sg|su
        Bseg b = {{sgT, sgT, suT, suT}, {0, 0, 1024, 1024}};
        fgemm<false><<<dim3(32, 8), 256, GEMM_SMEM>>>(
            xb, 1024, b, 1024, 0, sgu, 2048, nullptr, 1024, nullptr, nullptr, 0);
    }
    silu_pair_kernel<<<(T * SI + 255) / 256, 256>>>(sgu, act2, T * SI, 1024, 2048);
    {   // shared down
        Bseg b = {{sdT, sdT, sdT, sdT}, {0, 0, 0, 0}};
        fgemm<false><<<dim3(16, 8), 256, GEMM_SMEM>>>(
            act2, 1024, b, 1024, 0, sh, 1024, nullptr, 1024, nullptr, nullptr, 0);
    }

    final_kernel<<<(T * H + 255) / 256, 256>>>(h2, sh, edb, topkw, out);
}

// round 6
// speedup vs baseline: 1.2085x; 1.0615x over previous
#include <cuda_runtime.h>
#include <math.h>
#include <stdint.h>

#define T 1024
#define H 1024
#define NH 8
#define NKV 4
#define HD 128
#define NE 32
#define MI 512
#define SI 1024

// ---------------- scratch ----------------
__device__ float g_h1[T*H];
__device__ float g_qkv[T*2048];
__device__ float g_at[T*H];
__device__ float g_h2[T*H];
__device__ float g_xb[T*H];
__device__ float g_logits[T*NE];
__device__ float g_topkw[T*4];
__device__ int   g_cnt[NE];
__device__ int   g_list[NE*T];
__device__ float g_egu[4096*1024];      // expert-up out; also split-K partial buffer (2 x 1M)
__device__ float g_act[4096*512];
__device__ float g_edb[4096*1024];
__device__ float g_sgu[T*2048];
__device__ float g_act2[T*SI];
// K-major transposed weight copies (fp32)
__device__ float g_sgT[1024*1024];
__device__ float g_suT[1024*1024];
__device__ float g_sdT[1024*1024];
__device__ float g_egT[(size_t)NE*512*1024];
__device__ float g_euT[(size_t)NE*512*1024];
__device__ float g_edT[(size_t)NE*1024*512];

// ---------------- asm helpers ----------------
__device__ __forceinline__ void cp16(uint32_t d, const void* s) {
    asm volatile("cp.async.cg.shared.global [%0], [%1], 16;" :: "r"(d), "l"(s));
}
__device__ __forceinline__ void cp_commit() {
    asm volatile("cp.async.commit_group;" ::: "memory");
}
__device__ __forceinline__ void cp_wait1() {
    asm volatile("cp.async.wait_group 1;" ::: "memory");
}
__device__ __forceinline__ void cp_wait0() {
    asm volatile("cp.async.wait_group 0;" ::: "memory");
}
// packed fp32x2 FMA
__device__ __forceinline__ void fma2(unsigned long long& c, unsigned long long a,
                                     unsigned long long b) {
    asm("fma.rn.f32x2 %0, %1, %2, %0;" : "+l"(c) : "l"(a), "l"(b));
}
union U64F2 { unsigned long long u; float2 f; };

// ---------------- packed-fp32 GEMM: 128x128 tile, 8x8 microtile ----------------
// C[M,N] = A[M,K] @ B^T (B is [N][K] K-major). k-pairs packed in fma.rn.f32x2.
// GATHER: blockIdx.z = expert; rows via token lists.
// KSPLIT: blockIdx.z = k-split index; C += z*zstride, k += z*K.
struct Bseg { const float* p[4]; int base[4]; };

#define TS_F 4608                 // 128 rows x 36 floats
#define GEMM_SMEM (TS_F * 4 * 4)  // A,B x 2 stages x 4 bytes

template <bool GATHER, bool KSPLIT>
__global__ __launch_bounds__(256)
void fgemm(const float* __restrict__ A, int lda, Bseg Bs, int ldb, size_t estride,
           float* __restrict__ C, int ldc, size_t zstride, int K,
           const int* __restrict__ cnt, const int* __restrict__ list, int shift) {
    extern __shared__ __align__(16) float smemf[];
    __shared__ int rows_s[128];
    const int tid = threadIdx.x;
    const int tx = tid & 15, ty = tid >> 4;
    const int n0 = blockIdx.x * 128;
    const int m0 = blockIdx.y * 128;
    int e = 0, kbase = 0;
    if (GATHER) e = blockIdx.z;
    if (KSPLIT) { kbase = blockIdx.z * K; C += (size_t)blockIdx.z * zstride; }

    if (GATHER) {
        int me = cnt[e];
        if (m0 >= me) return;
        if (tid < 128) rows_s[tid] = (m0 + tid < me) ? list[e * T + m0 + tid] : -1;
        __syncthreads();
    }
    const int sgi = n0 >> 9;
    const float* Bp = Bs.p[sgi] + (size_t)e * estride;
    const int nb0 = n0 - Bs.base[sgi];
    const uint32_t sb = (uint32_t)__cvta_generic_to_shared(smemf);

    auto load_stage = [&](int cc, int slot) {
        const int k0 = kbase + cc * 32;
        const uint32_t sA = sb + slot * (TS_F * 4);
        const uint32_t sB = sb + (2 * TS_F + slot * TS_F) * 4;
#pragma unroll
        for (int it = 0; it < 4; it++) {
            int idx = tid + it * 256;
            int r = idx >> 3, ch = idx & 7;
            size_t arow;
            if (GATHER) { int j = rows_s[r]; arow = (j < 0) ? 0 : (size_t)(j >> shift); }
            else arow = (size_t)(m0 + r);
            cp16(sA + r * 144 + ch * 16, A + arow * lda + k0 + ch * 4);
            cp16(sB + r * 144 + ch * 16, Bp + (size_t)(nb0 + r) * ldb + k0 + ch * 4);
        }
    };

    unsigned long long acc[8][8];
#pragma unroll
    for (int i = 0; i < 8; i++)
#pragma unroll
        for (int j = 0; j < 8; j++) acc[i][j] = 0ull;

    const int nch = K >> 5;
    load_stage(0, 0); cp_commit();
    load_stage(1, 1); cp_commit();

    for (int c = 0; c < nch; c++) {
        if (c + 2 < nch) cp_wait1(); else cp_wait0();
        __syncthreads();
        const int slot = c & 1;
        const float* Ab = smemf + slot * TS_F;
        const float* Bb = smemf + (2 + slot) * TS_F;
#pragma unroll 4
        for (int kq = 0; kq < 8; kq++) {
            ulonglong2 bv[8];
#pragma unroll
            for (int j = 0; j < 8; j++)
                bv[j] = *(const ulonglong2*)&Bb[(j * 16 + tx) * 36 + kq * 4];
#pragma unroll
            for (int i = 0; i < 8; i++) {
                ulonglong2 av = *(const ulonglong2*)&Ab[(ty * 8 + i) * 36 + kq * 4];
#pragma unroll
                for (int j = 0; j < 8; j++) {
                    fma2(acc[i][j], av.x, bv[j].x);
                    fma2(acc[i][j], av.y, bv[j].y);
                }
            }
        }
        __syncthreads();
        if (c + 2 < nch) { load_stage(c + 2, slot); cp_commit(); }
    }

    // epilogue: fold k-pairs, store
#pragma unroll
    for (int i = 0; i < 8; i++) {
        int lr = ty * 8 + i;
        float* crow;
        if (GATHER) {
            int jj = rows_s[lr];
            if (jj < 0) continue;
            crow = C + (size_t)jj * ldc;
        } else {
            crow = C + (size_t)(m0 + lr) * ldc;
        }
#pragma unroll
        for (int j = 0; j < 8; j++) {
            U64F2 u; u.u = acc[i][j];
            crow[n0 + j * 16 + tx] = u.f.x + u.f.y;
        }
    }
}

// ---------------- weight transpose ----------------
__global__ void transpose_w(const float* __restrict__ src, float* __restrict__ dst,
                            int K, int N, size_t sstride, size_t dstride) {
    __shared__ float tile[32][33];
    int e = blockIdx.z;
    const float* sp = src + (size_t)e * sstride;
    float* dp = dst + (size_t)e * dstride;
    int k0 = blockIdx.y * 32, n0 = blockIdx.x * 32;
    int tx = threadIdx.x, ty = threadIdx.y;
#pragma unroll
    for (int i = 0; i < 4; i++)
        tile[ty + i * 8][tx] = sp[(size_t)(k0 + ty + i * 8) * N + n0 + tx];
    __syncthreads();
#pragma unroll
    for (int i = 0; i < 4; i++)
        dp[(size_t)(n0 + ty + i * 8) * K + k0 + tx] = tile[tx][ty + i * 8];
}

// ---------------- elementwise / norms ----------------
__global__ void rmsnorm_kernel(const float* __restrict__ x, const float* __restrict__ w,
                               float* __restrict__ out) {
    int t = blockIdx.x;
    const float* xr = x + (size_t)t * H;
    float s = 0.f;
    for (int i = threadIdx.x; i < H; i += blockDim.x) { float v = xr[i]; s += v * v; }
    __shared__ float red[32];
    for (int o = 16; o; o >>= 1) s += __shfl_xor_sync(0xffffffffu, s, o);
    if ((threadIdx.x & 31) == 0) red[threadIdx.x >> 5] = s;
    __syncthreads();
    if (threadIdx.x < 32) {
        float v = (threadIdx.x < (blockDim.x >> 5)) ? red[threadIdx.x] : 0.f;
        for (int o = 16; o; o >>= 1) v += __shfl_xor_sync(0xffffffffu, v, o);
        if (threadIdx.x == 0) red[0] = v;
    }
    __syncthreads();
    float inv = rsqrtf(red[0] * (1.f / H) + 1e-6f);
    for (int i = threadIdx.x; i < H; i += blockDim.x)
        out[(size_t)t * H + i] = xr[i] * inv * w[i];
}

__global__ void add3_kernel(const float* __restrict__ a, const float* __restrict__ b,
                            const float* __restrict__ c, float* __restrict__ o, int n) {
    int i = blockIdx.x * blockDim.x + threadIdx.x;
    if (i < n) o[i] = a[i] + b[i] + c[i];
}

__global__ void silu_pair_kernel(const float* __restrict__ x, float* __restrict__ o,
                                 int total, int w, int ldx) {
    int idx = blockIdx.x * blockDim.x + threadIdx.x;
    if (idx >= total) return;
    int r = idx / w, c = idx - r * w;
    float g = x[(size_t)r * ldx + c];
    float u = x[(size_t)r * ldx + w + c];
    o[idx] = g / (1.f + __expf(-g)) * u;
}

__global__ void zero_cnt_kernel(int* cnt) { if (threadIdx.x < NE) cnt[threadIdx.x] = 0; }

__global__ void rope_kernel(float* __restrict__ qkv, const int* __restrict__ pos) {
    int t = blockIdx.x;
    int i = threadIdx.x;
    int hh = threadIdx.y;
    float p = (float)pos[t];
    float inv = exp2f(-(float)i * (13.287712379549449f / 64.f));
    float sv, cv;
    sincosf(p * inv, &sv, &cv);
    float* base = (hh < 8) ? (qkv + (size_t)t * 2048 + hh * HD)
                           : (qkv + (size_t)t * 2048 + 1024 + (hh - 8) * HD);
    float x1 = base[i], x2 = base[i + 64];
    base[i]      = x1 * cv - x2 * sv;
    base[i + 64] = x2 * cv + x1 * sv;
}

// ---------------- causal flash attention (fp32) ----------------
__global__ void attn_kernel(const float* __restrict__ qkv, float* __restrict__ out) {
    const int h = blockIdx.x;
    const int qt = gridDim.y - 1 - blockIdx.y;
    const int kvh = h >> 1;
    const int warp = threadIdx.x >> 5, lane = threadIdx.x & 31;
    __shared__ float Ks[32][HD];
    __shared__ float Vs[32][HD];
    const int q0 = qt * 32 + warp * 4;
    float qr[4][4];
#pragma unroll
    for (int i = 0; i < 4; i++) {
        float4 f = *(const float4*)(qkv + (size_t)(q0 + i) * 2048 + h * HD + lane * 4);
        qr[i][0] = f.x; qr[i][1] = f.y; qr[i][2] = f.z; qr[i][3] = f.w;
    }
    float acc[4][4] = {};
    float mx[4] = {-1e30f, -1e30f, -1e30f, -1e30f};
    float ls[4] = {0.f, 0.f, 0.f, 0.f};
    const float scale = 0.088388347648318447f;
    for (int kt = 0; kt <= qt; kt++) {
        __syncthreads();
        for (int r = warp; r < 32; r += 8) {
            int kr = kt * 32 + r;
            *(float4*)&Ks[r][lane * 4] =
                *(const float4*)(qkv + (size_t)kr * 2048 + 1024 + kvh * HD + lane * 4);
            *(float4*)&Vs[r][lane * 4] =
                *(const float4*)(qkv + (size_t)kr * 2048 + 1536 + kvh * HD + lane * 4);
        }
        __syncthreads();
        const bool diag = (kt == qt);
        for (int j = 0; j < 32; j++) {
            const int kg = kt * 32 + j;
            float kv0 = Ks[j][lane*4+0], kv1 = Ks[j][lane*4+1];
            float kv2 = Ks[j][lane*4+2], kv3 = Ks[j][lane*4+3];
            float4 vv = *(const float4*)&Vs[j][lane * 4];
#pragma unroll
            for (int i = 0; i < 4; i++) {
                if (diag && kg > q0 + i) continue;
                float p = qr[i][0]*kv0 + qr[i][1]*kv1 + qr[i][2]*kv2 + qr[i][3]*kv3;
                p += __shfl_xor_sync(0xffffffffu, p, 16);
                p += __shfl_xor_sync(0xffffffffu, p, 8);
                p += __shfl_xor_sync(0xffffffffu, p, 4);
                p += __shfl_xor_sync(0xffffffffu, p, 2);
                p += __shfl_xor_sync(0xffffffffu, p, 1);
                float sc = p * scale;
                if (sc > mx[i]) {
                    float cc = __expf(mx[i] - sc);
                    ls[i] = ls[i] * cc + 1.f;
                    acc[i][0] = acc[i][0]*cc + vv.x; acc[i][1] = acc[i][1]*cc + vv.y;
                    acc[i][2] = acc[i][2]*cc + vv.z; acc[i][3] = acc[i][3]*cc + vv.w;
                    mx[i] = sc;
                } else {
                    float ee = __expf(sc - mx[i]);
                    ls[i] += ee;
                    acc[i][0] += ee*vv.x; acc[i][1] += ee*vv.y;
                    acc[i][2] += ee*vv.z; acc[i][3] += ee*vv.w;
                }
            }
        }
    }
#pragma unroll
    for (int i = 0; i < 4; i++) {
        float inv = 1.f / ls[i];
        float4 o = make_float4(acc[i][0]*inv, acc[i][1]*inv, acc[i][2]*inv, acc[i][3]*inv);
        *(float4*)(out + (size_t)(q0 + i) * H + h * HD + lane * 4) = o;
    }
}

// ---------------- router ----------------
__global__ void router_gemm(const float* __restrict__ xb, const float* __restrict__ rw,
                            float* __restrict__ logits) {
    __shared__ float xr[H];
    int t = blockIdx.x;
    for (int i = threadIdx.x; i < H; i += 128) xr[i] = xb[(size_t)t * H + i];
    __syncthreads();
    int w = threadIdx.x >> 5, lane = threadIdx.x & 31;
    for (int e8 = 0; e8 < 8; e8++) {
        int e = w * 8 + e8;
        const float* wr = rw + (size_t)e * H;
        float s = 0.f;
        for (int k = lane; k < H; k += 32) s += xr[k] * wr[k];
        for (int o = 16; o; o >>= 1) s += __shfl_xor_sync(0xffffffffu, s, o);
        if (lane == 0) logits[t * NE + e] = s;
    }
}

__global__ void router_kernel(const float* __restrict__ logits, const float* __restrict__ bias,
                              float* __restrict__ topkw, int* __restrict__ cnt,
                              int* __restrict__ list) {
    int t = blockIdx.x * blockDim.x + threadIdx.x;
    if (t >= T) return;
    float sc[NE], sfc[NE];
#pragma unroll
    for (int e = 0; e < NE; e++) {
        float l = logits[t * NE + e];
        float s = 1.f / (1.f + __expf(-l));
        sc[e] = s; sfc[e] = s + bias[e];
    }
    float gs[8];
#pragma unroll
    for (int g = 0; g < 8; g++) {
        float v[4] = {sfc[g*4+0], sfc[g*4+1], sfc[g*4+2], sfc[g*4+3]};
        float sum = v[0] + v[1] + v[2] + v[3];
        int mi = 0;
        for (int i = 1; i < 4; i++) if (v[i] < v[mi]) mi = i;
        float m2 = 1e30f;
        for (int i = 0; i < 4; i++) if (i != mi && v[i] < m2) m2 = v[i];
        gs[g] = sum - v[mi] - m2;
    }
    bool gsel[8] = {};
    for (int r = 0; r < 4; r++) {
        float best = -1e30f; int bi = 0;
        for (int g = 0; g < 8; g++) if (!gsel[g] && gs[g] > best) { best = gs[g]; bi = g; }
        gsel[bi] = true;
    }
    float masked[NE];
#pragma unroll
    for (int e = 0; e < NE; e++) masked[e] = gsel[e >> 2] ? sfc[e] : 0.f;
    int idxs[4]; float ws[4]; float wsum = 0.f;
    for (int r = 0; r < 4; r++) {
        float best = -1e30f; int bi = 0;
        for (int e = 0; e < NE; e++) if (masked[e] > best) { best = masked[e]; bi = e; }
        masked[bi] = -1e30f;
        idxs[r] = bi; ws[r] = sc[bi]; wsum += ws[r];
    }
    float inv = 2.5f / (wsum + 1e-20f);
    for (int r = 0; r < 4; r++) {
        topkw[t * 4 + r] = ws[r] * inv;
        int pos = atomicAdd(&cnt[idxs[r]], 1);
        list[idxs[r] * T + pos] = t * 4 + r;
    }
}

// final: out = h2 + shared_down(p0+p1) + sum_k tw*ed
__global__ void final_kernel(const float* __restrict__ h2, const float* __restrict__ p0,
                             const float* __restrict__ p1, const float* __restrict__ ed,
                             const float* __restrict__ tw, float* __restrict__ out) {
    int idx = blockIdx.x * blockDim.x + threadIdx.x;
    if (idx >= T * H) return;
    int t = idx >> 10;
    int hh = idx & 1023;
    float r = h2[idx] + p0[idx] + p1[idx];
#pragma unroll
    for (int kk = 0; kk < 4; kk++)
        r += tw[t * 4 + kk] * ed[(size_t)(t * 4 + kk) * H + hh];
    out[idx] = r;
}

// ---------------- host ----------------
extern "C" void kernel_launch(void* const* d_in, const int* in_sizes, int n_in,
                              void* d_out, int out_size) {
    (void)in_sizes; (void)n_in; (void)out_size;
    const float* hidden   = (const float*)d_in[0];
    const int*   pos      = (const int*)d_in[1];
    const float* ln1_w    = (const float*)d_in[2];
    const float* ln2_w    = (const float*)d_in[3];
    const float* q_w      = (const float*)d_in[4];
    const float* k_w      = (const float*)d_in[5];
    const float* v_w      = (const float*)d_in[6];
    const float* o_w      = (const float*)d_in[7];
    const float* router_w = (const float*)d_in[8];
    const float* r_bias   = (const float*)d_in[9];
    const float* eg_w     = (const float*)d_in[10];
    const float* eu_w     = (const float*)d_in[11];
    const float* ed_w     = (const float*)d_in[12];
    const float* sg_w     = (const float*)d_in[13];
    const float* su_w     = (const float*)d_in[14];
    const float* sd_w     = (const float*)d_in[15];
    float* out = (float*)d_out;

#define GSYM(p, s) cudaGetSymbolAddress((void**)&p, s)
    float *h1, *qkv, *at, *h2, *xb, *logits, *topkw, *egu, *act, *edb, *sgu, *act2;
    float *sgT, *suT, *sdT, *egT, *euT, *edT;
    int *cnt, *list;
    GSYM(h1,g_h1); GSYM(qkv,g_qkv); GSYM(at,g_at); GSYM(h2,g_h2); GSYM(xb,g_xb);
    GSYM(logits,g_logits); GSYM(topkw,g_topkw); GSYM(cnt,g_cnt); GSYM(list,g_list);
    GSYM(egu,g_egu); GSYM(act,g_act); GSYM(edb,g_edb);
    GSYM(sgu,g_sgu); GSYM(act2,g_act2);
    GSYM(sgT,g_sgT); GSYM(suT,g_suT); GSYM(sdT,g_sdT);
    GSYM(egT,g_egT); GSYM(euT,g_euT); GSYM(edT,g_edT);
#undef GSYM
    float* part0 = egu;               // split-K partial buffers (reused)
    float* part1 = egu + (size_t)T * H;

    cudaFuncSetAttribute(fgemm<false,false>, cudaFuncAttributeMaxDynamicSharedMemorySize, GEMM_SMEM);
    cudaFuncSetAttribute(fgemm<false,true>,  cudaFuncAttributeMaxDynamicSharedMemorySize, GEMM_SMEM);
    cudaFuncSetAttribute(fgemm<true,false>,  cudaFuncAttributeMaxDynamicSharedMemorySize, GEMM_SMEM);

    // launches 1-6 arranged so ncu (-s 5 -c 1) captures the O-proj GEMM (#6)
    zero_cnt_kernel<<<1, 32>>>(cnt);                                        // 1
    rmsnorm_kernel<<<T, 256>>>(hidden, ln1_w, h1);                          // 2
    {   // 3: fused QKV (weights native [N][K])
        Bseg b = {{q_w, q_w, k_w, v_w}, {0, 0, 1024, 1536}};
        fgemm<false,false><<<dim3(16, 8), 256, GEMM_SMEM>>>(
            h1, 1024, b, 1024, 0, qkv, 2048, 0, 1024, nullptr, nullptr, 0);
    }
    rope_kernel<<<T, dim3(64, 12)>>>(qkv, pos);                             // 4
    attn_kernel<<<dim3(NH, T / 32), 256>>>(qkv, at);                        // 5
    {   // 6: O projection, split-K=2 -> partials
        Bseg b = {{o_w, o_w, o_w, o_w}, {0, 0, 0, 0}};
        fgemm<false,true><<<dim3(8, 8, 2), 256, GEMM_SMEM>>>(
            at, 1024, b, 1024, 0, part0, 1024, (size_t)T * H, 512, nullptr, nullptr, 0);
    }
    add3_kernel<<<(T * H + 255) / 256, 256>>>(hidden, part0, part1, h2, T * H);  // 7

    // ---- weight transposes (8-13) ----
    transpose_w<<<dim3(32, 32, 1), dim3(32, 8)>>>(sg_w, sgT, 1024, 1024, 0, 0);
    transpose_w<<<dim3(32, 32, 1), dim3(32, 8)>>>(su_w, suT, 1024, 1024, 0, 0);
    transpose_w<<<dim3(32, 32, 1), dim3(32, 8)>>>(sd_w, sdT, 1024, 1024, 0, 0);
    transpose_w<<<dim3(16, 32, NE), dim3(32, 8)>>>(eg_w, egT, 1024, 512,
                                                   (size_t)1024*512, (size_t)512*1024);
    transpose_w<<<dim3(16, 32, NE), dim3(32, 8)>>>(eu_w, euT, 1024, 512,
                                                   (size_t)1024*512, (size_t)512*1024);
    transpose_w<<<dim3(32, 16, NE), dim3(32, 8)>>>(ed_w, edT, 512, 1024,
                                                   (size_t)512*1024, (size_t)1024*512);

    // ---- MoE branch ----
    rmsnorm_kernel<<<T, 256>>>(h2, ln2_w, xb);
    router_gemm<<<T, 128>>>(xb, router_w, logits);
    router_kernel<<<(T + 255) / 256, 256>>>(logits, r_bias, topkw, cnt, list);

    {   // routed experts up: fused eg|eu (gather)
        Bseg b = {{egT, euT, egT, euT}, {0, 512, 0, 512}};
        fgemm<true,false><<<dim3(8, 8, NE), 256, GEMM_SMEM>>>(
            xb, 1024, b, 1024, (size_t)512*1024, egu, 1024, 0, 1024, cnt, list, 2);
    }
    silu_pair_kernel<<<(4096 * 512 + 255) / 256, 256>>>(egu, act, 4096 * 512, 512, 1024);
    {   // expert down (gather)
        Bseg b = {{edT, edT, edT, edT}, {0, 0, 0, 0}};
        fgemm<true,false><<<dim3(8, 8, NE), 256, GEMM_SMEM>>>(
            act, 512, b, 512, (size_t)1024*512, edb, 1024, 0, 512, cnt, list, 0);
    }

    {   // shared expert up: fused sg|su
        Bseg b = {{sgT, sgT, suT, suT}, {0, 0, 1024, 1024}};
        fgemm<false,false><<<dim3(16, 8), 256, GEMM_SMEM>>>(
            xb, 1024, b, 1024, 0, sgu, 2048, 0, 1024, nullptr, nullptr, 0);
    }
    silu_pair_kernel<<<(T * SI + 255) / 256, 256>>>(sgu, act2, T * SI, 1024, 2048);
    {   // shared down, split-K=2 -> partials (egu free again after silu)
        Bseg b = {{sdT, sdT, sdT, sdT}, {0, 0, 0, 0}};
        fgemm<false,true><<<dim3(8, 8, 2), 256, GEMM_SMEM>>>(
            act2, 1024, b, 1024, 0, part0, 1024, (size_t)T * H, 512, nullptr, nullptr, 0);
    }

    final_kernel<<<(T * H + 255) / 256, 256>>>(h2, part0, part1, edb, topkw, out);
}